// round 16
// baseline (speedup 1.0000x reference)
#include <cuda_runtime.h>
#include <cuda_fp16.h>
#include <cstdint>
#include <math.h>

#define SEQ 2048
#define DIM 2048
#define NH 16
#define HD 192
#define NOPE 128
#define ROPE 64
#define VD 128
#define QKLD (NH*HD)   // 3072
#define TBLK 64

// ---------------------------------------------------------------------------
// scratch (allocation-free __device__ globals)
// ---------------------------------------------------------------------------
__device__ __half g_xh [SEQ*DIM];
__device__ __half g_wqh[QKLD*DIM];
__device__ __half g_wkh[QKLD*DIM];
__device__ __half g_wvh[DIM*DIM];
__device__ __half g_woh[DIM*DIM];
__device__ __half g_qh [SEQ*QKLD];
__device__ __half g_kh [SEQ*QKLD];
__device__ __half g_vh [SEQ*DIM];
__device__ __half g_vth[DIM*SEQ];
__device__ __half g_oh [SEQ*DIM];

// ---------------------------------------------------------------------------
static __device__ __forceinline__ uint32_t s2u(const void* p) {
    uint32_t a;
    asm("{ .reg .u64 t; cvta.to.shared.u64 t, %1; cvt.u32.u64 %0, t; }" : "=r"(a) : "l"(p));
    return a;
}
static __device__ __forceinline__ uint32_t h2u(__half2 h) {
    uint32_t u;
    *(__half2*)&u = h;
    return u;
}
#define CPA16(dst, src) \
    asm volatile("cp.async.cg.shared.global [%0], [%1], 16;" :: "r"(dst), "l"(src))
#define CPCOMMIT() asm volatile("cp.async.commit_group;" ::: "memory")
#define CPWAIT1()  asm volatile("cp.async.wait_group 1;" ::: "memory")
#define CPWAIT2()  asm volatile("cp.async.wait_group 2;" ::: "memory")

#define LDMX4(r0, r1, r2, r3, a) \
    asm volatile("ldmatrix.sync.aligned.m8n8.x4.shared.b16 {%0,%1,%2,%3}, [%4];" \
                 : "=r"(r0), "=r"(r1), "=r"(r2), "=r"(r3) : "r"(a))

#define MMA16816(d, a, b) \
    asm volatile("mma.sync.aligned.m16n8k16.row.col.f32.f16.f16.f32 " \
                 "{%0,%1,%2,%3},{%4,%5,%6,%7},{%8,%9},{%0,%1,%2,%3};" \
                 : "+f"((d)[0]), "+f"((d)[1]), "+f"((d)[2]), "+f"((d)[3]) \
                 : "r"((a)[0]), "r"((a)[1]), "r"((a)[2]), "r"((a)[3]), \
                   "r"((b)[0]), "r"((b)[1]))

// ---------------------------------------------------------------------------
// Wide HMMA GEMM core:  C[tile] = A * B^T  (K-major), fp16 operands.
//   Tile 128x256, 512 threads (16 warps as 4m x 4n of 32x64).
//   K-chunk 64 (row = 128B data + 16B pad = 144B), 3-stage cp.async pipeline.
//   CMODE: 0 = fp32 out, 2 = fp16 out.
// Smem: 3 stages x (128+256) rows x 144B = 165888 B, 1 CTA/SM.
// ---------------------------------------------------------------------------
template<int CMODE>
static __device__ __forceinline__ void
hgemm_core512(const __half* __restrict__ Ahz, const __half* __restrict__ Bhz,
              void* __restrict__ Cv,
              int m0, int n0, int kend, int lda, int ldb, int ldc)
{
    constexpr int ROWB  = 144;
    constexpr int ATILE = 128 * ROWB;          // 18432
    constexpr int BTILE = 256 * ROWB;          // 36864
    constexpr int STAGE = ATILE + BTILE;       // 55296

    extern __shared__ __align__(1024) char smem[];
    const uint32_t sb = s2u(smem);

    const int tid = threadIdx.x;
    const int w = tid >> 5, l = tid & 31;
    const int wm = w & 3, wn = w >> 2;         // 4 x 4 warps

    const int nst = kend >> 6;

    auto load_stage = [&](int s, int buf) {
        const int k0 = s << 6;
        const uint32_t st = sb + buf * STAGE;
        const __half* Ag = Ahz + (long long)m0 * lda + k0;
        #pragma unroll
        for (int i = 0; i < 2; i++) {          // A: 1024 chunks
            const int c = tid + (i << 9);
            const int row = c >> 3, cb = (c & 7) << 4;
            CPA16(st + row * ROWB + cb,
                  (const char*)(Ag + (long long)row * lda) + cb);
        }
        const __half* Bg = Bhz + (long long)n0 * ldb + k0;
        #pragma unroll
        for (int i = 0; i < 4; i++) {          // B: 2048 chunks
            const int c = tid + (i << 9);
            const int row = c >> 3, cb = (c & 7) << 4;
            CPA16(st + ATILE + row * ROWB + cb,
                  (const char*)(Bg + (long long)row * ldb) + cb);
        }
    };

    float acc[2][8][4];
    #pragma unroll
    for (int i = 0; i < 2; i++)
        #pragma unroll
        for (int j = 0; j < 8; j++)
            #pragma unroll
            for (int c = 0; c < 4; c++) acc[i][j][c] = 0.f;

    #pragma unroll
    for (int i = 0; i < 2; i++) {
        if (i < nst) load_stage(i, i);
        CPCOMMIT();
    }

    const int arow = (l & 7) + ((l >> 3) & 1) * 8;
    const int akb0 = ((l >> 4) & 1) * 16;
    const int brow = (l & 7) + ((l >> 4) & 1) * 8;
    const int bkb0 = ((l >> 3) & 1) * 16;

    for (int s = 0; s < nst; s++) {
        CPWAIT1();
        __syncthreads();
        if (s + 2 < nst) load_stage(s + 2, (s + 2) % 3);
        CPCOMMIT();

        const uint32_t st = sb + (s % 3) * STAGE;
        #pragma unroll
        for (int kt = 0; kt < 4; kt++) {
            uint32_t b[8][2];
            #pragma unroll
            for (int np = 0; np < 4; np++) {
                const int row = wn * 64 + np * 16 + brow;
                LDMX4(b[np*2][0], b[np*2][1], b[np*2+1][0], b[np*2+1][1],
                      st + ATILE + row * ROWB + kt * 32 + bkb0);
            }
            uint32_t a[2][4];
            #pragma unroll
            for (int mt = 0; mt < 2; mt++) {
                const int row = wm * 32 + mt * 16 + arow;
                LDMX4(a[mt][0], a[mt][1], a[mt][2], a[mt][3],
                      st + row * ROWB + kt * 32 + akb0);
            }
            #pragma unroll
            for (int mt = 0; mt < 2; mt++)
                #pragma unroll
                for (int nt = 0; nt < 8; nt++)
                    MMA16816(acc[mt][nt], a[mt], b[nt]);
        }
    }

    #pragma unroll
    for (int mt = 0; mt < 2; mt++) {
        #pragma unroll
        for (int nt = 0; nt < 8; nt++) {
            const int row = m0 + wm * 32 + mt * 16 + (l >> 2);
            const int col = n0 + wn * 64 + nt * 8 + (l & 3) * 2;
            const float c0 = acc[mt][nt][0], c1 = acc[mt][nt][1];
            const float c2 = acc[mt][nt][2], c3 = acc[mt][nt][3];
            if (CMODE == 2) {
                __half* Ch = (__half*)Cv;
                *(__half2*)(Ch + (long long)row * ldc + col) =
                    __floats2half2_rn(c0, c1);
                *(__half2*)(Ch + (long long)(row + 8) * ldc + col) =
                    __floats2half2_rn(c2, c3);
            } else {
                float* Cf = (float*)Cv;
                *(float2*)(Cf + (long long)row * ldc + col)       = make_float2(c0, c1);
                *(float2*)(Cf + (long long)(row + 8) * ldc + col) = make_float2(c2, c3);
            }
        }
    }
}

// ---------------------------------------------------------------------------
// WO GEMM wrapper (128x256 tiles)
// ---------------------------------------------------------------------------
template<int CMODE>
__global__ void __launch_bounds__(512, 1)
hgemm(const __half* __restrict__ Ah, const __half* __restrict__ Bh,
      void* __restrict__ Cv, int K, int lda, int ldb, int ldc)
{
    hgemm_core512<CMODE>(Ah, Bh, Cv, blockIdx.y * 128, blockIdx.x * 256,
                         K, lda, ldb, ldc);
}

// ---------------------------------------------------------------------------
// fused QKV projection (128x256 tiles): z=0 Q (12 nb), z=1 K (12), z=2 V (8)
// ---------------------------------------------------------------------------
__global__ void __launch_bounds__(512, 1)
hgemm_qkv(const __half* __restrict__ xh,
          const __half* __restrict__ wqh, const __half* __restrict__ wkh,
          const __half* __restrict__ wvh,
          __half* __restrict__ qh, __half* __restrict__ kh,
          __half* __restrict__ vh)
{
    const int z = blockIdx.z;
    const __half* B; __half* Ch; int nb, ldc;
    if (z == 0)      { B = wqh; Ch = qh; nb = 12; ldc = QKLD; }
    else if (z == 1) { B = wkh; Ch = kh; nb = 12; ldc = QKLD; }
    else             { B = wvh; Ch = vh; nb = 8;  ldc = DIM;  }
    if ((int)blockIdx.x >= nb) return;

    hgemm_core512<2>(xh, B, Ch, blockIdx.y * 128, blockIdx.x * 256,
                     DIM, DIM, DIM, ldc);
}

// ---------------------------------------------------------------------------
// fused flash attention: scores + causal online-softmax + PV in one kernel.
// grid (16 m-blocks, 16 heads), 256 threads, 1 CTA/SM, big m-blocks first.
// ---------------------------------------------------------------------------
__global__ void __launch_bounds__(256, 1)
flash_attn(const __half* __restrict__ Qg, const __half* __restrict__ Kg,
           const __half* __restrict__ Vt, __half* __restrict__ Og,
           float scale)
{
    constexpr int QROW = 400, KROW = 400, VROW = 144;
    constexpr int KOFF  = 128 * QROW;
    constexpr int KTILE = TBLK * KROW;
    constexpr int VOFF  = KOFF + 3 * KTILE;
    constexpr int VTILE = 128 * VROW;

    extern __shared__ __align__(1024) char smem[];
    const uint32_t sb = s2u(smem);

    const int m0 = (15 - (int)blockIdx.x) * 128;
    const int h  = blockIdx.y;
    const int tid = threadIdx.x;
    const int w = tid >> 5, l = tid & 31;

    const __half* Q = Qg + h * HD;
    const __half* K = Kg + h * HD;
    const __half* V = Vt + (long long)h * VD * SEQ;

    const int nst = (m0 >> 6) + 2;

    auto load_q = [&]() {
        #pragma unroll
        for (int i = 0; i < 12; i++) {
            int c = tid + (i << 8);
            int row = c / 24, cb = (c % 24) << 4;
            CPA16(sb + row * QROW + cb,
                  (const char*)(Q + (long long)(m0 + row) * QKLD) + cb);
        }
    };
    auto load_stage = [&](int s, int buf) {
        int t0 = s << 6;
        #pragma unroll
        for (int i = 0; i < 6; i++) {
            int c = tid + (i << 8);
            int row = c / 24, cb = (c % 24) << 4;
            CPA16(sb + KOFF + buf * KTILE + row * KROW + cb,
                  (const char*)(K + (long long)(t0 + row) * QKLD) + cb);
        }
        #pragma unroll
        for (int i = 0; i < 4; i++) {
            int c = tid + (i << 8);
            int row = c >> 3, cb = (c & 7) << 4;
            CPA16(sb + VOFF + buf * VTILE + row * VROW + cb,
                  (const char*)(V + (long long)row * SEQ + t0) + cb);
        }
    };

    load_q();          CPCOMMIT();
    load_stage(0, 0);  CPCOMMIT();
    load_stage(1, 1);  CPCOMMIT();

    const int arow = (l & 7) + ((l >> 3) & 1) * 8;
    const int akb0 = ((l >> 4) & 1) * 16;
    const int brow = (l & 7) + ((l >> 4) & 1) * 8;
    const int bkb0 = ((l >> 3) & 1) * 16;

    CPWAIT2();
    __syncthreads();
    uint32_t qf[12][4];
    #pragma unroll
    for (int ks = 0; ks < 12; ks++) {
        int row = w * 16 + arow;
        LDMX4(qf[ks][0], qf[ks][1], qf[ks][2], qf[ks][3],
              sb + row * QROW + ks * 32 + akb0);
    }

    float m1 = -1e30f, m2 = -1e30f, sum1 = 0.f, sum2 = 0.f;
    float oacc[16][4];
    #pragma unroll
    for (int i = 0; i < 16; i++)
        #pragma unroll
        for (int j = 0; j < 4; j++) oacc[i][j] = 0.f;

    const int q1 = m0 + w * 16 + (l >> 2);
    const int q2 = q1 + 8;

    for (int s = 0; s < nst; s++) {
        CPWAIT1();
        __syncthreads();
        if (s + 2 < nst) load_stage(s + 2, (s + 2) % 3);
        CPCOMMIT();

        const uint32_t kb = sb + KOFF + (s % 3) * KTILE;
        const uint32_t vb = sb + VOFF + (s % 3) * VTILE;
        const int t0 = s << 6;

        float sacc[8][4];
        #pragma unroll
        for (int i = 0; i < 8; i++)
            #pragma unroll
            for (int j = 0; j < 4; j++) sacc[i][j] = 0.f;
        #pragma unroll
        for (int ks = 0; ks < 12; ks++) {
            uint32_t bf[8][2];
            #pragma unroll
            for (int np = 0; np < 4; np++) {
                int row = np * 16 + brow;
                LDMX4(bf[np*2][0], bf[np*2][1], bf[np*2+1][0], bf[np*2+1][1],
                      kb + row * KROW + ks * 32 + bkb0);
            }
            #pragma unroll
            for (int nt = 0; nt < 8; nt++)
                MMA16816(sacc[nt], qf[ks], bf[nt]);
        }

        if (t0 + TBLK - 1 > m0) {
            #pragma unroll
            for (int nt = 0; nt < 8; nt++) {
                int t = t0 + nt * 8 + (l & 3) * 2;
                if (t     > q1) sacc[nt][0] = -1e30f;
                if (t + 1 > q1) sacc[nt][1] = -1e30f;
                if (t     > q2) sacc[nt][2] = -1e30f;
                if (t + 1 > q2) sacc[nt][3] = -1e30f;
            }
        }

        float mt1 = -1e30f, mt2 = -1e30f;
        #pragma unroll
        for (int nt = 0; nt < 8; nt++) {
            mt1 = fmaxf(mt1, fmaxf(sacc[nt][0], sacc[nt][1]));
            mt2 = fmaxf(mt2, fmaxf(sacc[nt][2], sacc[nt][3]));
        }
        mt1 = fmaxf(mt1, __shfl_xor_sync(0xffffffffu, mt1, 1));
        mt1 = fmaxf(mt1, __shfl_xor_sync(0xffffffffu, mt1, 2));
        mt2 = fmaxf(mt2, __shfl_xor_sync(0xffffffffu, mt2, 1));
        mt2 = fmaxf(mt2, __shfl_xor_sync(0xffffffffu, mt2, 2));
        const float m1n = fmaxf(m1, mt1), m2n = fmaxf(m2, mt2);
        const float f1 = __expf((m1 - m1n) * scale);
        const float f2 = __expf((m2 - m2n) * scale);
        m1 = m1n; m2 = m2n;
        if (!__all_sync(0xffffffffu, (f1 == 1.f) & (f2 == 1.f))) {
            #pragma unroll
            for (int nt = 0; nt < 16; nt++) {
                oacc[nt][0] *= f1; oacc[nt][1] *= f1;
                oacc[nt][2] *= f2; oacc[nt][3] *= f2;
            }
        }
        float st1 = 0.f, st2 = 0.f;
        #pragma unroll
        for (int nt = 0; nt < 8; nt++) {
            sacc[nt][0] = __expf((sacc[nt][0] - m1) * scale);
            sacc[nt][1] = __expf((sacc[nt][1] - m1) * scale);
            sacc[nt][2] = __expf((sacc[nt][2] - m2) * scale);
            sacc[nt][3] = __expf((sacc[nt][3] - m2) * scale);
            st1 += sacc[nt][0] + sacc[nt][1];
            st2 += sacc[nt][2] + sacc[nt][3];
        }
        st1 += __shfl_xor_sync(0xffffffffu, st1, 1);
        st1 += __shfl_xor_sync(0xffffffffu, st1, 2);
        st2 += __shfl_xor_sync(0xffffffffu, st2, 1);
        st2 += __shfl_xor_sync(0xffffffffu, st2, 2);
        sum1 = sum1 * f1 + st1;
        sum2 = sum2 * f2 + st2;

        uint32_t pf[4][4];
        #pragma unroll
        for (int kp = 0; kp < 4; kp++) {
            pf[kp][0] = h2u(__floats2half2_rn(sacc[2*kp][0],   sacc[2*kp][1]));
            pf[kp][1] = h2u(__floats2half2_rn(sacc[2*kp][2],   sacc[2*kp][3]));
            pf[kp][2] = h2u(__floats2half2_rn(sacc[2*kp+1][0], sacc[2*kp+1][1]));
            pf[kp][3] = h2u(__floats2half2_rn(sacc[2*kp+1][2], sacc[2*kp+1][3]));
        }

        #pragma unroll
        for (int kp = 0; kp < 4; kp++) {
            uint32_t bf[16][2];
            #pragma unroll
            for (int np = 0; np < 8; np++) {
                int row = np * 16 + brow;
                LDMX4(bf[np*2][0], bf[np*2][1], bf[np*2+1][0], bf[np*2+1][1],
                      vb + row * VROW + kp * 32 + bkb0);
            }
            #pragma unroll
            for (int nt = 0; nt < 16; nt++)
                MMA16816(oacc[nt], pf[kp], bf[nt]);
        }
    }

    const float i1 = 1.f / sum1, i2 = 1.f / sum2;
    __half* O1 = Og + (long long)q1 * DIM + h * VD;
    __half* O2 = Og + (long long)q2 * DIM + h * VD;
    #pragma unroll
    for (int nt = 0; nt < 16; nt++) {
        int col = nt * 8 + (l & 3) * 2;
        *(__half2*)(O1 + col) = __floats2half2_rn(oacc[nt][0] * i1, oacc[nt][1] * i1);
        *(__half2*)(O2 + col) = __floats2half2_rn(oacc[nt][2] * i2, oacc[nt][3] * i2);
    }
}

// ---------------------------------------------------------------------------
// fused fp32 -> fp16 (hi only), 16 elements/thread; z selects array
// ---------------------------------------------------------------------------
__global__ void f2h5(const float* __restrict__ x,
                     const float* __restrict__ wq, const float* __restrict__ wk,
                     const float* __restrict__ wv, const float* __restrict__ wo,
                     __half* __restrict__ ox,
                     __half* __restrict__ oq, __half* __restrict__ ok,
                     __half* __restrict__ ov, __half* __restrict__ oo)
{
    const int z = blockIdx.z;
    const float* in; __half* oh; int n;
    if (z == 0)      { in = x;  oh = ox; n = SEQ * DIM; }
    else if (z == 1) { in = wq; oh = oq; n = QKLD * DIM; }
    else if (z == 2) { in = wk; oh = ok; n = QKLD * DIM; }
    else if (z == 3) { in = wv; oh = ov; n = DIM * DIM; }
    else             { in = wo; oh = oo; n = DIM * DIM; }
    int i = (blockIdx.x * 256 + threadIdx.x) * 16;
    if (i >= n) return;
    float4 v0 = *(const float4*)(in + i);
    float4 v1 = *(const float4*)(in + i + 4);
    float4 v2 = *(const float4*)(in + i + 8);
    float4 v3 = *(const float4*)(in + i + 12);
    uint4 o0, o1;
    o0.x = h2u(__floats2half2_rn(v0.x, v0.y));
    o0.y = h2u(__floats2half2_rn(v0.z, v0.w));
    o0.z = h2u(__floats2half2_rn(v1.x, v1.y));
    o0.w = h2u(__floats2half2_rn(v1.z, v1.w));
    o1.x = h2u(__floats2half2_rn(v2.x, v2.y));
    o1.y = h2u(__floats2half2_rn(v2.z, v2.w));
    o1.z = h2u(__floats2half2_rn(v3.x, v3.y));
    o1.w = h2u(__floats2half2_rn(v3.z, v3.w));
    *(uint4*)(oh + i)     = o0;
    *(uint4*)(oh + i + 8) = o1;
}

// ---------------------------------------------------------------------------
// RoPE on pe slices of q, k (hi-only, half2 vectorized)
// ---------------------------------------------------------------------------
__global__ void rope_kernel(__half* __restrict__ Qh, __half* __restrict__ Kh,
                            const float* __restrict__ cosT, const float* __restrict__ sinT)
{
    int idx = blockIdx.x * blockDim.x + threadIdx.x;
    if (idx >= SEQ * NH * (ROPE / 2)) return;
    int i = idx & 31, h = (idx >> 5) & 15, s = idx >> 9;
    float c = cosT[s * 32 + i], sn = sinT[s * 32 + i];
    long long base = (long long)s * QKLD + h * HD + NOPE + 2 * i;
    __half2 q = *(__half2*)(Qh + base);
    float a = __half2float(__low2half(q)), b = __half2float(__high2half(q));
    *(__half2*)(Qh + base) = __floats2half2_rn(a * c - b * sn, a * sn + b * c);
    __half2 k = *(__half2*)(Kh + base);
    a = __half2float(__low2half(k)); b = __half2float(__high2half(k));
    *(__half2*)(Kh + base) = __floats2half2_rn(a * c - b * sn, a * sn + b * c);
}

// ---------------------------------------------------------------------------
__global__ void transpose_h(const __half* __restrict__ in, __half* __restrict__ out)
{
    __shared__ __half t[32][33];
    int x = blockIdx.x * 32 + threadIdx.x;
    int y = blockIdx.y * 32 + threadIdx.y;
    #pragma unroll
    for (int j = 0; j < 32; j += 8)
        t[threadIdx.y + j][threadIdx.x] = in[(long long)(y + j) * DIM + x];
    __syncthreads();
    x = blockIdx.y * 32 + threadIdx.x;
    y = blockIdx.x * 32 + threadIdx.y;
    #pragma unroll
    for (int j = 0; j < 32; j += 8)
        out[(long long)(y + j) * SEQ + x] = t[threadIdx.x][threadIdx.y + j];
}

// ---------------------------------------------------------------------------
extern "C" void kernel_launch(void* const* d_in, const int* in_sizes, int n_in,
                              void* d_out, int out_size)
{
    const float* x  = (const float*)d_in[0];
    const float* wq = (const float*)d_in[1];
    const float* wk = (const float*)d_in[2];
    const float* wv = (const float*)d_in[3];
    const float* wo = (const float*)d_in[4];
    const float* fc = (const float*)d_in[5];
    const float* fs = (const float*)d_in[6];
    float* out = (float*)d_out;

    __half *xh, *wqh, *wkh, *wvh, *woh;
    __half *qh, *kh, *vh, *vth, *oh;
    cudaGetSymbolAddress((void**)&xh, g_xh);
    cudaGetSymbolAddress((void**)&wqh, g_wqh);
    cudaGetSymbolAddress((void**)&wkh, g_wkh);
    cudaGetSymbolAddress((void**)&wvh, g_wvh);
    cudaGetSymbolAddress((void**)&woh, g_woh);
    cudaGetSymbolAddress((void**)&qh, g_qh);
    cudaGetSymbolAddress((void**)&kh, g_kh);
    cudaGetSymbolAddress((void**)&vh, g_vh);
    cudaGetSymbolAddress((void**)&vth, g_vth);
    cudaGetSymbolAddress((void**)&oh, g_oh);

    const int SMEMW = 3 * 55296;   // 165888: wide 128x256 tiles
    const int SMEMF = 183296;      // flash_attn
    cudaFuncSetAttribute((const void*)hgemm_qkv, cudaFuncAttributeMaxDynamicSharedMemorySize, SMEMW);
    cudaFuncSetAttribute((const void*)hgemm<0>,  cudaFuncAttributeMaxDynamicSharedMemorySize, SMEMW);
    cudaFuncSetAttribute((const void*)flash_attn, cudaFuncAttributeMaxDynamicSharedMemorySize, SMEMF);

    // fused conversions: x + 4 weights, fp16 hi only
    f2h5<<<dim3(QKLD * DIM / 4096, 1, 5), 256>>>(x, wq, wk, wv, wo,
                                                 xh, wqh, wkh, wvh, woh);

    // fused QKV projections (128x256 tiles), all fp16 out
    hgemm_qkv<<<dim3(12, 16, 3), 512, SMEMW>>>(xh, wqh, wkh, wvh, qh, kh, vh);

    // RoPE (hi-only, half2)
    rope_kernel<<<(SEQ * NH * 32 + 255) / 256, 256>>>(qh, kh, fc, fs);

    // V transpose -> [DIM][SEQ] K-major for flash PV
    transpose_h<<<dim3(64, 64), dim3(32, 8)>>>(vh, vth);

    // fused attention: scores + causal softmax + PV (big m-blocks first)
    flash_attn<<<dim3(16, 16), 256, SMEMF>>>(qh, kh, vth, oh, rsqrtf((float)HD));

    // output projection (128x256 tiles): fp16 in, fp32 out
    hgemm<0><<<dim3(DIM / 256, SEQ / 128), 512, SMEMW>>>(
        oh, woh, out, DIM, DIM, DIM, DIM);
}

// round 17
// speedup vs baseline: 1.0884x; 1.0884x over previous
#include <cuda_runtime.h>
#include <cuda_fp16.h>
#include <cstdint>
#include <math.h>

#define SEQ 2048
#define DIM 2048
#define NH 16
#define HD 192
#define NOPE 128
#define ROPE 64
#define VD 128
#define QKLD (NH*HD)   // 3072
#define TBLK 64

// ---------------------------------------------------------------------------
// scratch (allocation-free __device__ globals)
// ---------------------------------------------------------------------------
__device__ __half g_xh [SEQ*DIM];
__device__ __half g_wqh[QKLD*DIM];
__device__ __half g_wkh[QKLD*DIM];
__device__ __half g_wvh[DIM*DIM];
__device__ __half g_woh[DIM*DIM];
__device__ __half g_qh [SEQ*QKLD];
__device__ __half g_kh [SEQ*QKLD];
__device__ __half g_vh [SEQ*DIM];
__device__ __half g_oh [SEQ*DIM];

// ---------------------------------------------------------------------------
static __device__ __forceinline__ uint32_t s2u(const void* p) {
    uint32_t a;
    asm("{ .reg .u64 t; cvta.to.shared.u64 t, %1; cvt.u32.u64 %0, t; }" : "=r"(a) : "l"(p));
    return a;
}
static __device__ __forceinline__ uint32_t h2u(__half2 h) {
    uint32_t u;
    *(__half2*)&u = h;
    return u;
}
#define CPA16(dst, src) \
    asm volatile("cp.async.cg.shared.global [%0], [%1], 16;" :: "r"(dst), "l"(src))
#define CPCOMMIT() asm volatile("cp.async.commit_group;" ::: "memory")
#define CPWAIT1()  asm volatile("cp.async.wait_group 1;" ::: "memory")
#define CPWAIT2()  asm volatile("cp.async.wait_group 2;" ::: "memory")

#define LDMX4(r0, r1, r2, r3, a) \
    asm volatile("ldmatrix.sync.aligned.m8n8.x4.shared.b16 {%0,%1,%2,%3}, [%4];" \
                 : "=r"(r0), "=r"(r1), "=r"(r2), "=r"(r3) : "r"(a))

#define LDMX4T(r0, r1, r2, r3, a) \
    asm volatile("ldmatrix.sync.aligned.m8n8.x4.trans.shared.b16 {%0,%1,%2,%3}, [%4];" \
                 : "=r"(r0), "=r"(r1), "=r"(r2), "=r"(r3) : "r"(a))

#define MMA16816(d, a, b) \
    asm volatile("mma.sync.aligned.m16n8k16.row.col.f32.f16.f16.f32 " \
                 "{%0,%1,%2,%3},{%4,%5,%6,%7},{%8,%9},{%0,%1,%2,%3};" \
                 : "+f"((d)[0]), "+f"((d)[1]), "+f"((d)[2]), "+f"((d)[3]) \
                 : "r"((a)[0]), "r"((a)[1]), "r"((a)[2]), "r"((a)[3]), \
                   "r"((b)[0]), "r"((b)[1]))

// ---------------------------------------------------------------------------
// HMMA GEMM core:  C[tile] = A * B^T  (K-major), pure fp16 operands.
//   Tile 128x128, 256 threads, warp tile 32x64, K-chunk 64, 3-stage pipeline.
//   CMODE: 0 = fp32 out, 2 = fp16 out.
// ---------------------------------------------------------------------------
template<int CMODE>
static __device__ __forceinline__ void
hgemm_core(const __half* __restrict__ Ahz, const __half* __restrict__ Bhz,
           void* __restrict__ Cv,
           int m0, int n0, int kend, int lda, int ldb, int ldc)
{
    constexpr int ROWB  = 144;
    constexpr int TILE  = 128 * ROWB;
    constexpr int STAGE = 2 * TILE;

    extern __shared__ __align__(1024) char smem[];
    const uint32_t sb = s2u(smem);

    const int tid = threadIdx.x;
    const int w = tid >> 5, l = tid & 31;
    const int wm = w & 3, wn = w >> 2;

    const int nst = kend >> 6;

    auto load_tile = [&](const __half* G, int ld, uint32_t dstbase) {
        #pragma unroll
        for (int i = 0; i < 4; i++) {
            const int c = tid + (i << 8);
            const int row = c >> 3;
            const int cb  = (c & 7) << 4;
            CPA16(dstbase + row * ROWB + cb,
                  (const char*)(G + (long long)row * ld) + cb);
        }
    };

    auto load_stage = [&](int s, int buf) {
        const int k0 = s << 6;
        const uint32_t st = sb + buf * STAGE;
        load_tile(Ahz + (long long)m0 * lda + k0, lda, st);
        load_tile(Bhz + (long long)n0 * ldb + k0, ldb, st + TILE);
    };

    float acc[2][8][4];
    #pragma unroll
    for (int i = 0; i < 2; i++)
        #pragma unroll
        for (int j = 0; j < 8; j++)
            #pragma unroll
            for (int c = 0; c < 4; c++) acc[i][j][c] = 0.f;

    #pragma unroll
    for (int i = 0; i < 2; i++) {
        if (i < nst) load_stage(i, i);
        CPCOMMIT();
    }

    const int arow = (l & 7) + ((l >> 3) & 1) * 8;
    const int akb0 = ((l >> 4) & 1) * 16;
    const int brow = (l & 7) + ((l >> 4) & 1) * 8;
    const int bkb0 = ((l >> 3) & 1) * 16;

    for (int s = 0; s < nst; s++) {
        CPWAIT1();
        __syncthreads();
        if (s + 2 < nst) load_stage(s + 2, (s + 2) % 3);
        CPCOMMIT();

        const uint32_t st = sb + (s % 3) * STAGE;
        #pragma unroll
        for (int kt = 0; kt < 4; kt++) {
            uint32_t b[8][2];
            #pragma unroll
            for (int np = 0; np < 4; np++) {
                const int row = wn * 64 + np * 16 + brow;
                LDMX4(b[np*2][0], b[np*2][1], b[np*2+1][0], b[np*2+1][1],
                      st + TILE + row * ROWB + kt * 32 + bkb0);
            }
            uint32_t a[2][4];
            #pragma unroll
            for (int mt = 0; mt < 2; mt++) {
                const int row = wm * 32 + mt * 16 + arow;
                LDMX4(a[mt][0], a[mt][1], a[mt][2], a[mt][3],
                      st + row * ROWB + kt * 32 + akb0);
            }
            #pragma unroll
            for (int mt = 0; mt < 2; mt++)
                #pragma unroll
                for (int nt = 0; nt < 8; nt++)
                    MMA16816(acc[mt][nt], a[mt], b[nt]);
        }
    }

    #pragma unroll
    for (int mt = 0; mt < 2; mt++) {
        #pragma unroll
        for (int nt = 0; nt < 8; nt++) {
            const int row = m0 + wm * 32 + mt * 16 + (l >> 2);
            const int col = n0 + wn * 64 + nt * 8 + (l & 3) * 2;
            const float c0 = acc[mt][nt][0], c1 = acc[mt][nt][1];
            const float c2 = acc[mt][nt][2], c3 = acc[mt][nt][3];
            if (CMODE == 2) {
                __half* Ch = (__half*)Cv;
                *(__half2*)(Ch + (long long)row * ldc + col) =
                    __floats2half2_rn(c0, c1);
                *(__half2*)(Ch + (long long)(row + 8) * ldc + col) =
                    __floats2half2_rn(c2, c3);
            } else {
                float* Cf = (float*)Cv;
                *(float2*)(Cf + (long long)row * ldc + col)       = make_float2(c0, c1);
                *(float2*)(Cf + (long long)(row + 8) * ldc + col) = make_float2(c2, c3);
            }
        }
    }
}

// ---------------------------------------------------------------------------
// WO GEMM wrapper
// ---------------------------------------------------------------------------
template<int CMODE>
__global__ void __launch_bounds__(256, 2)
hgemm(const __half* __restrict__ Ah, const __half* __restrict__ Bh,
      void* __restrict__ Cv, int K, int lda, int ldb, int ldc)
{
    hgemm_core<CMODE>(Ah, Bh, Cv, blockIdx.y * 128, blockIdx.x * 128,
                      K, lda, ldb, ldc);
}

// ---------------------------------------------------------------------------
// fused QKV projection: z=0 Q, z=1 K, z=2 V
// ---------------------------------------------------------------------------
__global__ void __launch_bounds__(256, 2)
hgemm_qkv(const __half* __restrict__ xh,
          const __half* __restrict__ wqh, const __half* __restrict__ wkh,
          const __half* __restrict__ wvh,
          __half* __restrict__ qh, __half* __restrict__ kh,
          __half* __restrict__ vh)
{
    const int z = blockIdx.z;
    const __half* B; __half* Ch; int nb, ldc;
    if (z == 0)      { B = wqh; Ch = qh; nb = 24; ldc = QKLD; }
    else if (z == 1) { B = wkh; Ch = kh; nb = 24; ldc = QKLD; }
    else             { B = wvh; Ch = vh; nb = 16; ldc = DIM;  }
    if ((int)blockIdx.x >= nb) return;

    hgemm_core<2>(xh, B, Ch, blockIdx.y * 128, blockIdx.x * 128,
                  DIM, DIM, DIM, ldc);
}

// ---------------------------------------------------------------------------
// fused flash attention: scores + causal online-softmax + PV in one kernel.
// grid (16 m-blocks, 16 heads), 256 threads, 1 CTA/SM, big m-blocks first.
// V consumed in NATURAL [SEQ][DIM] layout via ldmatrix.trans (no transpose).
// ---------------------------------------------------------------------------
__global__ void __launch_bounds__(256, 1)
flash_attn(const __half* __restrict__ Qg, const __half* __restrict__ Kg,
           const __half* __restrict__ Vg, __half* __restrict__ Og,
           float scale)
{
    constexpr int QROW = 400, KROW = 400, VROW = 272;   // V: 256B data + 16B pad
    constexpr int KOFF  = 128 * QROW;           // 51200
    constexpr int KTILE = TBLK * KROW;          // 25600
    constexpr int VOFF  = KOFF + 3 * KTILE;     // 128000
    constexpr int VTILE = TBLK * VROW;          // 17408

    extern __shared__ __align__(1024) char smem[];
    const uint32_t sb = s2u(smem);

    const int m0 = (15 - (int)blockIdx.x) * 128;   // big blocks first
    const int h  = blockIdx.y;
    const int tid = threadIdx.x;
    const int w = tid >> 5, l = tid & 31;

    const __half* Q = Qg + h * HD;                 // row stride QKLD
    const __half* K = Kg + h * HD;
    const __half* V = Vg + h * VD;                 // natural layout, row stride DIM

    const int nst = (m0 >> 6) + 2;

    auto load_q = [&]() {
        #pragma unroll
        for (int i = 0; i < 12; i++) {       // 128 rows x 24 16B-chunks
            int c = tid + (i << 8);
            int row = c / 24, cb = (c % 24) << 4;
            CPA16(sb + row * QROW + cb,
                  (const char*)(Q + (long long)(m0 + row) * QKLD) + cb);
        }
    };
    auto load_stage = [&](int s, int buf) {
        int t0 = s << 6;
        #pragma unroll
        for (int i = 0; i < 6; i++) {        // K: 64 rows x 24 chunks
            int c = tid + (i << 8);
            int row = c / 24, cb = (c % 24) << 4;
            CPA16(sb + KOFF + buf * KTILE + row * KROW + cb,
                  (const char*)(K + (long long)(t0 + row) * QKLD) + cb);
        }
        #pragma unroll
        for (int i = 0; i < 4; i++) {        // V: 64 t-rows x 16 chunks (256B)
            int c = tid + (i << 8);
            int row = c >> 4, cb = (c & 15) << 4;
            CPA16(sb + VOFF + buf * VTILE + row * VROW + cb,
                  (const char*)(V + (long long)(t0 + row) * DIM) + cb);
        }
    };

    load_q();          CPCOMMIT();
    load_stage(0, 0);  CPCOMMIT();
    load_stage(1, 1);  CPCOMMIT();

    const int arow = (l & 7) + ((l >> 3) & 1) * 8;
    const int akb0 = ((l >> 4) & 1) * 16;
    const int brow = (l & 7) + ((l >> 4) & 1) * 8;
    const int bkb0 = ((l >> 3) & 1) * 16;
    // trans-ldmatrix lane coords for V ([t][n] storage)
    const int vrow = (l & 7) + ((l >> 3) & 1) * 8;    // k (t) offset within 16
    const int vcb0 = ((l >> 4) & 1) * 16;             // n offset (bytes)

    CPWAIT2();
    __syncthreads();
    uint32_t qf[12][4];
    #pragma unroll
    for (int ks = 0; ks < 12; ks++) {
        int row = w * 16 + arow;
        LDMX4(qf[ks][0], qf[ks][1], qf[ks][2], qf[ks][3],
              sb + row * QROW + ks * 32 + akb0);
    }

    float m1 = -1e30f, m2 = -1e30f, sum1 = 0.f, sum2 = 0.f;
    float oacc[16][4];
    #pragma unroll
    for (int i = 0; i < 16; i++)
        #pragma unroll
        for (int j = 0; j < 4; j++) oacc[i][j] = 0.f;

    const int q1 = m0 + w * 16 + (l >> 2);
    const int q2 = q1 + 8;

    for (int s = 0; s < nst; s++) {
        CPWAIT1();
        __syncthreads();
        if (s + 2 < nst) load_stage(s + 2, (s + 2) % 3);
        CPCOMMIT();

        const uint32_t kb = sb + KOFF + (s % 3) * KTILE;
        const uint32_t vb = sb + VOFF + (s % 3) * VTILE;
        const int t0 = s << 6;

        // ---- S = Q K^T ----
        float sacc[8][4];
        #pragma unroll
        for (int i = 0; i < 8; i++)
            #pragma unroll
            for (int j = 0; j < 4; j++) sacc[i][j] = 0.f;
        #pragma unroll
        for (int ks = 0; ks < 12; ks++) {
            uint32_t bf[8][2];
            #pragma unroll
            for (int np = 0; np < 4; np++) {
                int row = np * 16 + brow;
                LDMX4(bf[np*2][0], bf[np*2][1], bf[np*2+1][0], bf[np*2+1][1],
                      kb + row * KROW + ks * 32 + bkb0);
            }
            #pragma unroll
            for (int nt = 0; nt < 8; nt++)
                MMA16816(sacc[nt], qf[ks], bf[nt]);
        }

        // ---- causal mask (partial blocks only) ----
        if (t0 + TBLK - 1 > m0) {
            #pragma unroll
            for (int nt = 0; nt < 8; nt++) {
                int t = t0 + nt * 8 + (l & 3) * 2;
                if (t     > q1) sacc[nt][0] = -1e30f;
                if (t + 1 > q1) sacc[nt][1] = -1e30f;
                if (t     > q2) sacc[nt][2] = -1e30f;
                if (t + 1 > q2) sacc[nt][3] = -1e30f;
            }
        }

        // ---- online softmax update ----
        float mt1 = -1e30f, mt2 = -1e30f;
        #pragma unroll
        for (int nt = 0; nt < 8; nt++) {
            mt1 = fmaxf(mt1, fmaxf(sacc[nt][0], sacc[nt][1]));
            mt2 = fmaxf(mt2, fmaxf(sacc[nt][2], sacc[nt][3]));
        }
        mt1 = fmaxf(mt1, __shfl_xor_sync(0xffffffffu, mt1, 1));
        mt1 = fmaxf(mt1, __shfl_xor_sync(0xffffffffu, mt1, 2));
        mt2 = fmaxf(mt2, __shfl_xor_sync(0xffffffffu, mt2, 1));
        mt2 = fmaxf(mt2, __shfl_xor_sync(0xffffffffu, mt2, 2));
        const float m1n = fmaxf(m1, mt1), m2n = fmaxf(m2, mt2);
        const float f1 = __expf((m1 - m1n) * scale);
        const float f2 = __expf((m2 - m2n) * scale);
        m1 = m1n; m2 = m2n;
        if (!__all_sync(0xffffffffu, (f1 == 1.f) & (f2 == 1.f))) {
            #pragma unroll
            for (int nt = 0; nt < 16; nt++) {
                oacc[nt][0] *= f1; oacc[nt][1] *= f1;
                oacc[nt][2] *= f2; oacc[nt][3] *= f2;
            }
        }
        float st1 = 0.f, st2 = 0.f;
        #pragma unroll
        for (int nt = 0; nt < 8; nt++) {
            sacc[nt][0] = __expf((sacc[nt][0] - m1) * scale);
            sacc[nt][1] = __expf((sacc[nt][1] - m1) * scale);
            sacc[nt][2] = __expf((sacc[nt][2] - m2) * scale);
            sacc[nt][3] = __expf((sacc[nt][3] - m2) * scale);
            st1 += sacc[nt][0] + sacc[nt][1];
            st2 += sacc[nt][2] + sacc[nt][3];
        }
        st1 += __shfl_xor_sync(0xffffffffu, st1, 1);
        st1 += __shfl_xor_sync(0xffffffffu, st1, 2);
        st2 += __shfl_xor_sync(0xffffffffu, st2, 1);
        st2 += __shfl_xor_sync(0xffffffffu, st2, 2);
        sum1 = sum1 * f1 + st1;
        sum2 = sum2 * f2 + st2;

        // ---- P fragments (C-frag -> A-frag, fp16) ----
        uint32_t pf[4][4];
        #pragma unroll
        for (int kp = 0; kp < 4; kp++) {
            pf[kp][0] = h2u(__floats2half2_rn(sacc[2*kp][0],   sacc[2*kp][1]));
            pf[kp][1] = h2u(__floats2half2_rn(sacc[2*kp][2],   sacc[2*kp][3]));
            pf[kp][2] = h2u(__floats2half2_rn(sacc[2*kp+1][0], sacc[2*kp+1][1]));
            pf[kp][3] = h2u(__floats2half2_rn(sacc[2*kp+1][2], sacc[2*kp+1][3]));
        }

        // ---- O += P V  (V natural [t][n], trans-ldmatrix B frags) ----
        #pragma unroll
        for (int kp = 0; kp < 4; kp++) {
            const uint32_t vk = vb + (kp * 16 + vrow) * VROW + vcb0;
            #pragma unroll
            for (int np = 0; np < 8; np++) {
                uint32_t b0[2], b1[2];
                LDMX4T(b0[0], b0[1], b1[0], b1[1], vk + np * 32);
                MMA16816(oacc[2*np],     pf[kp], b0);
                MMA16816(oacc[2*np + 1], pf[kp], b1);
            }
        }
    }

    // ---- normalize + write O (fp16) ----
    const float i1 = 1.f / sum1, i2 = 1.f / sum2;
    __half* O1 = Og + (long long)q1 * DIM + h * VD;
    __half* O2 = Og + (long long)q2 * DIM + h * VD;
    #pragma unroll
    for (int nt = 0; nt < 16; nt++) {
        int col = nt * 8 + (l & 3) * 2;
        *(__half2*)(O1 + col) = __floats2half2_rn(oacc[nt][0] * i1, oacc[nt][1] * i1);
        *(__half2*)(O2 + col) = __floats2half2_rn(oacc[nt][2] * i2, oacc[nt][3] * i2);
    }
}

// ---------------------------------------------------------------------------
// fused fp32 -> fp16 (hi only), 16 elements/thread; z selects array
// ---------------------------------------------------------------------------
__global__ void f2h5(const float* __restrict__ x,
                     const float* __restrict__ wq, const float* __restrict__ wk,
                     const float* __restrict__ wv, const float* __restrict__ wo,
                     __half* __restrict__ ox,
                     __half* __restrict__ oq, __half* __restrict__ ok,
                     __half* __restrict__ ov, __half* __restrict__ oo)
{
    const int z = blockIdx.z;
    const float* in; __half* oh; int n;
    if (z == 0)      { in = x;  oh = ox; n = SEQ * DIM; }
    else if (z == 1) { in = wq; oh = oq; n = QKLD * DIM; }
    else if (z == 2) { in = wk; oh = ok; n = QKLD * DIM; }
    else if (z == 3) { in = wv; oh = ov; n = DIM * DIM; }
    else             { in = wo; oh = oo; n = DIM * DIM; }
    int i = (blockIdx.x * 256 + threadIdx.x) * 16;
    if (i >= n) return;
    float4 v0 = *(const float4*)(in + i);
    float4 v1 = *(const float4*)(in + i + 4);
    float4 v2 = *(const float4*)(in + i + 8);
    float4 v3 = *(const float4*)(in + i + 12);
    uint4 o0, o1;
    o0.x = h2u(__floats2half2_rn(v0.x, v0.y));
    o0.y = h2u(__floats2half2_rn(v0.z, v0.w));
    o0.z = h2u(__floats2half2_rn(v1.x, v1.y));
    o0.w = h2u(__floats2half2_rn(v1.z, v1.w));
    o1.x = h2u(__floats2half2_rn(v2.x, v2.y));
    o1.y = h2u(__floats2half2_rn(v2.z, v2.w));
    o1.z = h2u(__floats2half2_rn(v3.x, v3.y));
    o1.w = h2u(__floats2half2_rn(v3.z, v3.w));
    *(uint4*)(oh + i)     = o0;
    *(uint4*)(oh + i + 8) = o1;
}

// ---------------------------------------------------------------------------
// RoPE on pe slices of q, k (hi-only, half2 vectorized)
// ---------------------------------------------------------------------------
__global__ void rope_kernel(__half* __restrict__ Qh, __half* __restrict__ Kh,
                            const float* __restrict__ cosT, const float* __restrict__ sinT)
{
    int idx = blockIdx.x * blockDim.x + threadIdx.x;
    if (idx >= SEQ * NH * (ROPE / 2)) return;
    int i = idx & 31, h = (idx >> 5) & 15, s = idx >> 9;
    float c = cosT[s * 32 + i], sn = sinT[s * 32 + i];
    long long base = (long long)s * QKLD + h * HD + NOPE + 2 * i;
    __half2 q = *(__half2*)(Qh + base);
    float a = __half2float(__low2half(q)), b = __half2float(__high2half(q));
    *(__half2*)(Qh + base) = __floats2half2_rn(a * c - b * sn, a * sn + b * c);
    __half2 k = *(__half2*)(Kh + base);
    a = __half2float(__low2half(k)); b = __half2float(__high2half(k));
    *(__half2*)(Kh + base) = __floats2half2_rn(a * c - b * sn, a * sn + b * c);
}

// ---------------------------------------------------------------------------
extern "C" void kernel_launch(void* const* d_in, const int* in_sizes, int n_in,
                              void* d_out, int out_size)
{
    const float* x  = (const float*)d_in[0];
    const float* wq = (const float*)d_in[1];
    const float* wk = (const float*)d_in[2];
    const float* wv = (const float*)d_in[3];
    const float* wo = (const float*)d_in[4];
    const float* fc = (const float*)d_in[5];
    const float* fs = (const float*)d_in[6];
    float* out = (float*)d_out;

    __half *xh, *wqh, *wkh, *wvh, *woh;
    __half *qh, *kh, *vh, *oh;
    cudaGetSymbolAddress((void**)&xh, g_xh);
    cudaGetSymbolAddress((void**)&wqh, g_wqh);
    cudaGetSymbolAddress((void**)&wkh, g_wkh);
    cudaGetSymbolAddress((void**)&wvh, g_wvh);
    cudaGetSymbolAddress((void**)&woh, g_woh);
    cudaGetSymbolAddress((void**)&qh, g_qh);
    cudaGetSymbolAddress((void**)&kh, g_kh);
    cudaGetSymbolAddress((void**)&vh, g_vh);
    cudaGetSymbolAddress((void**)&oh, g_oh);

    const int SMEM  = 3 * 36864;   // 110592 (hgemm, 2 CTAs/SM)
    const int SMEMF = 128000 + 3 * 17408;  // 180224 (flash_attn)
    cudaFuncSetAttribute((const void*)hgemm_qkv, cudaFuncAttributeMaxDynamicSharedMemorySize, SMEM);
    cudaFuncSetAttribute((const void*)hgemm<0>,  cudaFuncAttributeMaxDynamicSharedMemorySize, SMEM);
    cudaFuncSetAttribute((const void*)flash_attn, cudaFuncAttributeMaxDynamicSharedMemorySize, SMEMF);

    // fused conversions: x + 4 weights, fp16 hi only
    f2h5<<<dim3(QKLD * DIM / 4096, 1, 5), 256>>>(x, wq, wk, wv, wo,
                                                 xh, wqh, wkh, wvh, woh);

    // fused QKV projections (128x128, 2 CTAs/SM), all fp16 out
    hgemm_qkv<<<dim3(24, 16, 3), 256, SMEM>>>(xh, wqh, wkh, wvh, qh, kh, vh);

    // RoPE (hi-only, half2)
    rope_kernel<<<(SEQ * NH * 32 + 255) / 256, 256>>>(qh, kh, fc, fs);

    // fused attention: scores + causal softmax + PV (V natural layout)
    flash_attn<<<dim3(16, 16), 256, SMEMF>>>(qh, kh, vh, oh, rsqrtf((float)HD));

    // output projection: fp16 in, fp32 out
    hgemm<0><<<dim3(DIM / 128, SEQ / 128), 256, SMEM>>>(
        oh, woh, out, DIM, DIM, DIM, DIM);
}